// round 1
// baseline (speedup 1.0000x reference)
#include <cuda_runtime.h>

#define FULL 0xffffffffu

// Scratch: per-(group, b, l) partial sums of the head reduction.
// 2 * 64 * 4096 * 4B = 2 MB static device global (allocation-free).
__device__ float g_partial[2][64][4096];

__device__ __forceinline__ float tanh_approx(float v) {
    float r;
    asm("tanh.approx.f32 %0, %1;" : "=f"(r) : "f"(v));
    return r;
}

// Kernel 1: scan + sigmoid + per-group head reduction.
// grid = (64 b, 2 head-groups), block = 512 threads (16 warps).
// Warp w owns heads i0..i0+3 (4 chains); lane owns 4 consecutive j per tile.
// Tile = 128 j's; 32 tiles cover N=4096.
__global__ __launch_bounds__(512, 1)
void nade_main_kernel(const float* __restrict__ x,
                      const float* __restrict__ W1,
                      const float* __restrict__ b1,
                      const float* __restrict__ W2)
{
    __shared__ float xs[4096];          // 16 KB: this b's x row
    __shared__ float red[2][16][128];   // 16 KB: double-buffered warp partials

    const int b    = blockIdx.x;
    const int g    = blockIdx.y;
    const int tid  = threadIdx.x;
    const int w    = tid >> 5;
    const int lane = tid & 31;

    // Preload x[b, :] into shared (coalesced float4).
    const float4* x4  = reinterpret_cast<const float4*>(x + b * 4096);
    float4*       xs4 = reinterpret_cast<float4*>(xs);
    for (int idx = tid; idx < 1024; idx += 512) xs4[idx] = x4[idx];
    __syncthreads();

    const int i0 = g * 64 + w * 4;

    // cb[h] = 0.5 * (running_exclusive_prefix + b1[i]); exact *0.5 scaling
    // lets sigmoid(x) = 0.5*tanh(0.5x)+0.5 use one fma for the argument.
    float cb[4];
    #pragma unroll
    for (int h = 0; h < 4; h++) cb[h] = 0.5f * b1[i0 + h];

    const float4* W1_4 = reinterpret_cast<const float4*>(W1);
    const float4* W2_4 = reinterpret_cast<const float4*>(W2);

    for (int t = 0; t < 32; ++t) {
        const int j0 = t * 128;
        const int jv = (j0 >> 2) + lane;   // float4 index within a 4096 row
        const float4 xv = xs4[jv];
        float4 acc = make_float4(0.f, 0.f, 0.f, 0.f);

        #pragma unroll
        for (int h = 0; h < 4; h++) {
            const int i = i0 + h;
            const float4 w1 = W1_4[i * 1024 + jv];
            const float4 w2 = W2_4[i * 1024 + jv];

            // Per-lane products and local inclusive partials.
            const float p0 = xv.x * w1.x;
            const float p1 = xv.y * w1.y;
            const float p2 = xv.z * w1.z;
            const float p3 = xv.w * w1.w;
            const float s01  = p0 + p1;
            const float s012 = s01 + p2;
            const float s    = s012 + p3;

            // Warp inclusive scan of per-lane sums (5 shfl per 128 elems).
            float inc = s;
            #pragma unroll
            for (int o = 1; o < 32; o <<= 1) {
                const float v = __shfl_up_sync(FULL, inc, o);
                if (lane >= o) inc += v;
            }
            const float base = inc - s;              // exclusive lane base

            // sigmoid argument * 0.5, with carry+bias pre-folded.
            const float c2l = fmaf(0.5f, base, cb[h]);
            const float a0 = c2l;
            const float a1 = fmaf(0.5f, p0,   c2l);
            const float a2 = fmaf(0.5f, s01,  c2l);
            const float a3 = fmaf(0.5f, s012, c2l);

            const float t0 = tanh_approx(a0);
            const float t1 = tanh_approx(a1);
            const float t2 = tanh_approx(a2);
            const float t3 = tanh_approx(a3);

            acc.x = fmaf(fmaf(0.5f, t0, 0.5f), w2.x, acc.x);
            acc.y = fmaf(fmaf(0.5f, t1, 0.5f), w2.y, acc.y);
            acc.z = fmaf(fmaf(0.5f, t2, 0.5f), w2.z, acc.z);
            acc.w = fmaf(fmaf(0.5f, t3, 0.5f), w2.w, acc.w);

            // Advance chain carry by this tile's total.
            const float tot = __shfl_sync(FULL, inc, 31);
            cb[h] = fmaf(0.5f, tot, cb[h]);
        }

        // Stage this warp's 128 partials; one barrier per tile (double buffer).
        const int buf = t & 1;
        reinterpret_cast<float4*>(&red[buf][w][0])[lane] = acc;
        __syncthreads();

        // 4 reducer warps (rotating for balance) fold 16 warps -> 128 outputs.
        const int rbase = (t & 3) * 4;
        const int chunk = w - rbase;
        if (chunk >= 0 && chunk < 4) {
            const int l = chunk * 32 + lane;
            float sum = 0.f;
            #pragma unroll
            for (int ww = 0; ww < 16; ++ww) sum += red[buf][ww][l];
            g_partial[g][b][j0 + l] = sum;
        }
    }
}

// Kernel 2: combine group partials + b2, accurate final sigmoid.
__global__ void nade_final_kernel(const float* __restrict__ b2,
                                  float* __restrict__ out)
{
    const int idx = blockIdx.x * blockDim.x + threadIdx.x;  // 0..262143
    const int b = idx >> 12;
    const int l = idx & 4095;
    const float v = g_partial[0][b][l] + g_partial[1][b][l] + b2[l];
    out[idx] = 1.0f / (1.0f + __expf(-v));
}

extern "C" void kernel_launch(void* const* d_in, const int* in_sizes, int n_in,
                              void* d_out, int out_size)
{
    const float* x  = (const float*)d_in[0];
    const float* W1 = (const float*)d_in[1];
    const float* b1 = (const float*)d_in[2];
    const float* W2 = (const float*)d_in[3];
    const float* b2 = (const float*)d_in[4];

    dim3 grid(64, 2);
    nade_main_kernel<<<grid, 512>>>(x, W1, b1, W2);
    nade_final_kernel<<<1024, 256>>>(b2, (float*)d_out);
}